// round 8
// baseline (speedup 1.0000x reference)
#include <cuda_runtime.h>
#include <cstdint>

// NeighborPoolingLayer: out[m, :] = mean_{e in [splits[m], splits[m+1])} feat[nidx[e], :]
// feat: [N, 64] f32; nidx: [E] int32; splits: [M+1] int32; out: [M, 64] f32
// (JAX with default x64-disabled config downgrades the reference's int64 arrays
//  to int32 — reading them as int64 caused the R3 illegal access.)
//
// One warp per output row m. Each lane holds a float2 accumulator (2 channels).
// Each gathered row = 32 lanes x 8B = 256B = two perfectly coalesced 128B lines.
// Inner unroll x4, outer unroll x2 -> up to 8 independent gathers in flight.

static constexpr int C2 = 32;  // 64 floats = 32 float2 per row

__global__ __launch_bounds__(256) void neighbor_pool_kernel(
    const float2* __restrict__ feat2,        // [N, 32] as float2
    const int* __restrict__ nidx,            // [E]
    const int* __restrict__ splits,          // [M+1]
    float2* __restrict__ out2,               // [M, 32] as float2
    int M)
{
    const int warp = (blockIdx.x * blockDim.x + threadIdx.x) >> 5;
    const int lane = threadIdx.x & 31;
    if (warp >= M) return;

    const int start = splits[warp];
    const int end   = splits[warp + 1];
    const int count = end - start;

    float accx = 0.0f, accy = 0.0f;

    int e = start;
    // Unrolled by 4 (x2 outer): up to 8 independent gathered loads in flight.
    #pragma unroll 2
    for (; e + 4 <= end; e += 4) {
        const int i0 = nidx[e + 0] * C2 + lane;
        const int i1 = nidx[e + 1] * C2 + lane;
        const int i2 = nidx[e + 2] * C2 + lane;
        const int i3 = nidx[e + 3] * C2 + lane;
        const float2 a = __ldg(feat2 + i0);
        const float2 b = __ldg(feat2 + i1);
        const float2 c = __ldg(feat2 + i2);
        const float2 d = __ldg(feat2 + i3);
        accx += (a.x + b.x) + (c.x + d.x);
        accy += (a.y + b.y) + (c.y + d.y);
    }
    for (; e < end; ++e) {
        const int i = nidx[e] * C2 + lane;
        const float2 a = __ldg(feat2 + i);
        accx += a.x;
        accy += a.y;
    }

    const float inv = (count > 0) ? (1.0f / (float)count) : 0.0f;
    float2 r;
    r.x = accx * inv;
    r.y = accy * inv;
    out2[(size_t)warp * C2 + lane] = r;
}

extern "C" void kernel_launch(void* const* d_in, const int* in_sizes, int n_in,
                              void* d_out, int out_size)
{
    const float* feat   = (const float*)d_in[0];   // [N*64] f32
    const int*   nidx   = (const int*)d_in[1];     // [E] int32
    const int*   splits = (const int*)d_in[2];     // [M+1] int32
    float*       out    = (float*)d_out;           // [M*64] f32

    const int M = in_sizes[2] - 1;

    const int threads = 256;                 // 8 warps/block
    const int warps_per_block = threads / 32;
    const int blocks = (M + warps_per_block - 1) / warps_per_block;

    neighbor_pool_kernel<<<blocks, threads>>>(
        (const float2*)feat, nidx, splits, (float2*)out, M);
}